// round 5
// baseline (speedup 1.0000x reference)
#include <cuda_runtime.h>
#include <cstdint>
#include <math.h>

#define Bq 2
#define Lq 1024
#define Aq 14
#define Kq 30
#define EFq 128
#define EDGE_INq 3152
#define Mrows (Bq*Lq*Kq)      // 61440
#define BM 128
#define NCHUNK 99             // padded K = 3168

typedef uint32_t u32;

// ---- scratch ----
__device__ int g_Eidx[Mrows];
__device__ __align__(16) float g_X2[Bq*Lq*Aq*3];
__device__ __align__(16) float g_Wfrag[NCHUNK*4096];  // fragment-layout tf32 W

__constant__ float c_freq[8] = {
    1.0f, 0.31622776601683794f, 0.1f, 0.031622776601683794f,
    0.01f, 0.0031622776601683794f, 0.001f, 0.00031622776601683794f
};

__device__ __forceinline__ u32 f2tf32(float v) {
    u32 u; asm("cvt.rna.tf32.f32 %0, %1;" : "=r"(u) : "f"(v)); return u;
}
__device__ __forceinline__ void mma_tf32(float* d, const u32* a, const u32* b) {
    asm volatile("mma.sync.aligned.m16n8k8.row.col.f32.tf32.tf32.f32 "
        "{%0,%1,%2,%3}, {%4,%5,%6,%7}, {%8,%9}, {%0,%1,%2,%3};"
        : "+f"(d[0]), "+f"(d[1]), "+f"(d[2]), "+f"(d[3])
        : "r"(a[0]), "r"(a[1]), "r"(a[2]), "r"(a[3]), "r"(b[0]), "r"(b[1]));
}

// =====================================================================
// Kernel 1: topk (correct since round 1)
// =====================================================================
__global__ void topk_kernel(const float* __restrict__ X,
                            const float* __restrict__ mask,
                            float* __restrict__ out_tail) {
    __shared__ float Da[Lq];
    __shared__ float svals[8];
    __shared__ int   sidx[8];
    __shared__ float sDmax;

    int bi  = blockIdx.x;
    int b   = bi >> 10;
    int i   = bi & (Lq - 1);
    int tid = threadIdx.x;

    const float* Xb = X + (size_t)b * Lq * Aq * 3;
    float cx = Xb[(i*Aq+1)*3+0];
    float cy = Xb[(i*Aq+1)*3+1];
    float cz = Xb[(i*Aq+1)*3+2];
    float mi = mask[b*Lq + i];

    float lmax = 0.f;
    for (int j = tid; j < Lq; j += 256) {
        float dx = cx - Xb[(j*Aq+1)*3+0];
        float dy = cy - Xb[(j*Aq+1)*3+1];
        float dz = cz - Xb[(j*Aq+1)*3+2];
        float m2 = mi * mask[b*Lq + j];
        float D  = m2 * sqrtf(dx*dx + dy*dy + dz*dz + 1e-6f);
        Da[j] = D;
        lmax = fmaxf(lmax, D);
    }
    #pragma unroll
    for (int off = 16; off; off >>= 1)
        lmax = fmaxf(lmax, __shfl_xor_sync(0xffffffffu, lmax, off));
    if ((tid & 31) == 0) svals[tid >> 5] = lmax;
    __syncthreads();
    if (tid == 0) {
        float m = svals[0];
        for (int w = 1; w < 8; w++) m = fmaxf(m, svals[w]);
        sDmax = m;
    }
    __syncthreads();
    float Dmax = sDmax;
    for (int j = tid; j < Lq; j += 256) {
        float m2 = mi * mask[b*Lq + j];
        Da[j] += 2.f * (1.f - m2) * Dmax;
    }
    __syncthreads();

    for (int k = 0; k < Kq; k++) {
        float bv = 3.4e38f; int bj = 0x7fffffff;
        for (int j = tid; j < Lq; j += 256) {
            float v = Da[j];
            if (v < bv) { bv = v; bj = j; }
        }
        #pragma unroll
        for (int off = 16; off; off >>= 1) {
            float ov = __shfl_down_sync(0xffffffffu, bv, off);
            int   oj = __shfl_down_sync(0xffffffffu, bj, off);
            if (ov < bv || (ov == bv && oj < bj)) { bv = ov; bj = oj; }
        }
        if ((tid & 31) == 0) { svals[tid >> 5] = bv; sidx[tid >> 5] = bj; }
        __syncthreads();
        if (tid == 0) {
            for (int w = 1; w < 8; w++) {
                float v = svals[w]; int jj = sidx[w];
                if (v < bv || (v == bv && jj < bj)) { bv = v; bj = jj; }
            }
            int orow = bi * Kq + k;
            g_Eidx[orow] = bj;
            if (out_tail) out_tail[orow] = (float)bj;
            Da[bj] = 3.4e38f;
        }
        __syncthreads();
    }
}

// =====================================================================
// Kernel 2: build X2 with virtual Cb
// =====================================================================
__global__ void buildX2_kernel(const float* __restrict__ X) {
    int t = blockIdx.x * blockDim.x + threadIdx.x;
    if (t >= Bq * Lq) return;
    const float* xr = X + (size_t)t * Aq * 3;
    float* o = g_X2 + (size_t)t * Aq * 3;
    #pragma unroll
    for (int a = 0; a < Aq*3; a++) o[a] = xr[a];
    float Nx = xr[0],  Ny = xr[1],  Nz = xr[2];
    float Cax= xr[3],  Cay= xr[4],  Caz= xr[5];
    float Cx = xr[6],  Cy = xr[7],  Cz = xr[8];
    float bx = Cax - Nx, by = Cay - Ny, bz = Caz - Nz;
    float cx = Cx - Cax, cy = Cy - Cay, cz = Cz - Caz;
    float ax = by*cz - bz*cy;
    float ay = bz*cx - bx*cz;
    float az = bx*cy - by*cx;
    o[12] = -0.58273431f*ax + 0.56802827f*bx - 0.54067466f*cx + Cax;
    o[13] = -0.58273431f*ay + 0.56802827f*by - 0.54067466f*cy + Cay;
    o[14] = -0.58273431f*az + 0.56802827f*bz - 0.54067466f*cz + Caz;
}

// =====================================================================
// Kernel 3: pack W into mma fragment layout:
// g_Wfrag[k*4096 + wn*2048 + s*512 + lane*16 + nt*2 + half]
//   = tf32( W[n][c] ), n = wn*64+nt*8+(lane>>2), c = k*32+s*8+(lane&3)+half*4
// =====================================================================
__global__ void prepWfrag_kernel(const float* __restrict__ W) {
    int t = blockIdx.x * blockDim.x + threadIdx.x;
    if (t >= NCHUNK * 4096) return;
    int half = t & 1;
    int nt   = (t >> 1) & 7;
    int lane = (t >> 4) & 31;
    int s    = (t >> 9) & 3;
    int wn   = (t >> 11) & 1;
    int k    = t >> 12;
    int n = wn*64 + nt*8 + (lane >> 2);
    int c = k*32 + s*8 + (lane & 3) + half*4;
    float v = (c < EDGE_INq) ? W[(size_t)n * EDGE_INq + c] : 0.f;
    g_Wfrag[t] = __uint_as_float(f2tf32(v));
}

// =====================================================================
// Kernel 4: fused featuregen-in-registers + mma.sync tf32 + LayerNorm
// =====================================================================
// dynamic smem float offsets
#define OFF_SE    0        // 64*132 = 8448 (epilogue only)
#define OFF_SD    8448     // 2*256
#define OFF_SCO   8960     // 2*256
#define OFF_DPOS  9472     // 128
#define OFF_IIDX  9600
#define OFF_JIDX  9728
#define SM_TOTAL  (9856*4) // 39424 B
#define ESTRIDE   132

__global__ void __launch_bounds__(256, 2)
fused_hmma_kernel(const float* __restrict__ atom_mask,
                  const float* __restrict__ gamma_,
                  const float* __restrict__ beta_,
                  float* __restrict__ out) {
    extern __shared__ float sm[];
    float* sE    = sm + OFF_SE;
    float* sD    = sm + OFF_SD;     // [buf][l*128+row]
    float* sCo   = sm + OFF_SCO;
    float* dposS = sm + OFF_DPOS;
    int*   iidx  = (int*)(sm + OFF_IIDX);
    int*   jidx  = (int*)(sm + OFF_JIDX);

    int tid  = threadIdx.x;
    int wid  = tid >> 5, lane = tid & 31;
    int wm   = wid & 3, wn = wid >> 2;
    int lq   = lane >> 2;    // 0..7
    int lr   = lane & 3;     // 0..3
    int row0 = blockIdx.x * BM;

    if (tid < BM) {
        int gr  = row0 + tid;
        int b   = gr / (Lq * Kq);
        int rem = gr - b * (Lq * Kq);
        int i   = rem / Kq;
        int j   = g_Eidx[gr];
        iidx[tid] = b * Lq + i;
        jidx[tid] = b * Lq + j;
        dposS[tid] = (float)(j - i);
    }
    __syncthreads();

    // ---- stage chunk 0 D/co into buf 0 ----
    {
        int l = tid >> 7, row = tid & 127;
        int P = -1 + l;
        float D = 0.f, co = 0.f;
        if (P >= 0 && P < 196) {
            int p = P / 14, q = P - p * 14;
            const float* xi = g_X2 + iidx[row]*42 + p*3;
            const float* xj = g_X2 + jidx[row]*42 + q*3;
            float dx = xi[0]-xj[0], dy = xi[1]-xj[1], dz = xi[2]-xj[2];
            D  = sqrtf(dx*dx + dy*dy + dz*dz + 1e-6f);
            co = (1.f - atom_mask[iidx[row]*14 + p]) *
                 (1.f - atom_mask[jidx[row]*14 + q]);
        }
        sD [(l << 7) + row] = D;
        sCo[(l << 7) + row] = co;
    }
    __syncthreads();

    float acc[2][8][4];
    #pragma unroll
    for (int mt = 0; mt < 2; mt++)
        #pragma unroll
        for (int nt = 0; nt < 8; nt++)
            #pragma unroll
            for (int c = 0; c < 4; c++) acc[mt][nt][c] = 0.f;

    // posenc values (chunk 0 only) computed once, kept in regs
    float pe_c[2][4], pe_s[2][4];      // [freq half][row rr]
    {
        #pragma unroll
        for (int rr = 0; rr < 4; rr++) {
            int row = (wm << 5) + (rr << 3) + lq;
            float d = dposS[row];
            sincosf(d * c_freq[lr],     &pe_s[0][rr], &pe_c[0][rr]);
            sincosf(d * c_freq[lr + 4], &pe_s[1][rr], &pe_c[1][rr]);
        }
    }

    const float* wf = g_Wfrag;

    for (int k = 0; k < NCHUNK; k++) {
        int buf = k & 1;
        // ---- preload this chunk's D/co into registers ----
        float Dv[2][4], Cv[2][4];
        #pragma unroll
        for (int rr = 0; rr < 4; rr++) {
            int row = (wm << 5) + (rr << 3) + lq;
            Dv[0][rr] = sD [(buf << 8) + row];
            Dv[1][rr] = sD [(buf << 8) + 128 + row];
            Cv[0][rr] = sCo[(buf << 8) + row];
            Cv[1][rr] = sCo[(buf << 8) + 128 + row];
        }
        // ---- stage chunk k+1 into the other buffer ----
        if (k + 1 < NCHUNK) {
            int l = tid >> 7, row = tid & 127;
            int P = 2*(k+1) - 1 + l;
            float D = 0.f, co = 0.f;
            if (P < 196) {
                int p = P / 14, q = P - p * 14;
                const float* xi = g_X2 + iidx[row]*42 + p*3;
                const float* xj = g_X2 + jidx[row]*42 + q*3;
                float dx = xi[0]-xj[0], dy = xi[1]-xj[1], dz = xi[2]-xj[2];
                D  = sqrtf(dx*dx + dy*dy + dz*dz + 1e-6f);
                co = (1.f - atom_mask[iidx[row]*14 + p]) *
                     (1.f - atom_mask[jidx[row]*14 + q]);
            }
            sD [((buf^1) << 8) + (l << 7) + row] = D;
            sCo[((buf^1) << 8) + (l << 7) + row] = co;
        }
        // ---- fragment gen + mma ----
        #pragma unroll
        for (int s = 0; s < 4; s++) {
            // B fragments: 4 x LDG.128, exact register layout
            const float4* bp = (const float4*)(wf +
                ((((size_t)k*2 + wn)*4 + s)*32 + lane)*16);
            float4 q0 = bp[0], q1 = bp[1], q2 = bp[2], q3 = bp[3];
            u32 bfr[16] = {
                __float_as_uint(q0.x), __float_as_uint(q0.y),
                __float_as_uint(q0.z), __float_as_uint(q0.w),
                __float_as_uint(q1.x), __float_as_uint(q1.y),
                __float_as_uint(q1.z), __float_as_uint(q1.w),
                __float_as_uint(q2.x), __float_as_uint(q2.y),
                __float_as_uint(q2.z), __float_as_uint(q2.w),
                __float_as_uint(q3.x), __float_as_uint(q3.y),
                __float_as_uint(q3.z), __float_as_uint(q3.w) };
            const int l = s >> 1;
            // rbf params: r = (s&1)*8 + lr (+4); mu = r*4/3
            float mu0 = (float)((s & 1)*8 + lr) * 1.3333333333f;
            float mu1 = mu0 + 5.3333333333f;
            #pragma unroll
            for (int mt = 0; mt < 2; mt++) {
                u32 afr[4];
                if (k == 0 && s < 2) {
                    // posenc: s=0 -> cos, s=1 -> sin; freq idx lr / lr+4
                    if (s == 0) {
                        afr[0] = f2tf32(pe_c[0][mt*2  ]);
                        afr[1] = f2tf32(pe_c[0][mt*2+1]);
                        afr[2] = f2tf32(pe_c[1][mt*2  ]);
                        afr[3] = f2tf32(pe_c[1][mt*2+1]);
                    } else {
                        afr[0] = f2tf32(pe_s[0][mt*2  ]);
                        afr[1] = f2tf32(pe_s[0][mt*2+1]);
                        afr[2] = f2tf32(pe_s[1][mt*2  ]);
                        afr[3] = f2tf32(pe_s[1][mt*2+1]);
                    }
                } else {
                    float D0 = Dv[l][mt*2],   C0 = Cv[l][mt*2];
                    float D1 = Dv[l][mt*2+1], C1 = Cv[l][mt*2+1];
                    float x0 = (D0 - mu0) * 0.8f;
                    float x1 = (D1 - mu0) * 0.8f;
                    float x2 = (D0 - mu1) * 0.8f;
                    float x3 = (D1 - mu1) * 0.8f;
                    afr[0] = f2tf32(C0 * __expf(-x0*x0));
                    afr[1] = f2tf32(C1 * __expf(-x1*x1));
                    afr[2] = f2tf32(C0 * __expf(-x2*x2));
                    afr[3] = f2tf32(C1 * __expf(-x3*x3));
                }
                #pragma unroll
                for (int nt = 0; nt < 8; nt++)
                    mma_tf32(acc[mt][nt], afr, &bfr[nt*2]);
            }
        }
        __syncthreads();   // staged k+1 visible; buf free for k+2 staging
    }

    // ================= epilogue: 2 halves of 64 rows =================
    float4 g4 = *(const float4*)&gamma_[lane << 2];
    float4 b4 = *(const float4*)&beta_ [lane << 2];

    #pragma unroll
    for (int h = 0; h < 2; h++) {
        __syncthreads();
        if ((wm >> 1) == h) {
            #pragma unroll
            for (int mt = 0; mt < 2; mt++) {
                int rl = (wm << 5) + (mt << 4) + lq - (h << 6);
                #pragma unroll
                for (int nt = 0; nt < 8; nt++) {
                    int col = (wn << 6) + (nt << 3) + (lr << 1);
                    *(float2*)&sE[ rl      * ESTRIDE + col] =
                        make_float2(acc[mt][nt][0], acc[mt][nt][1]);
                    *(float2*)&sE[(rl + 8) * ESTRIDE + col] =
                        make_float2(acc[mt][nt][2], acc[mt][nt][3]);
                }
            }
        }
        __syncthreads();
        #pragma unroll
        for (int rr = 0; rr < 8; rr++) {
            int rl = (wid << 3) + rr;
            float4 v = *(const float4*)&sE[rl * ESTRIDE + (lane << 2)];
            float s  = v.x + v.y + v.z + v.w;
            float sq = v.x*v.x + v.y*v.y + v.z*v.z + v.w*v.w;
            #pragma unroll
            for (int off = 16; off; off >>= 1) {
                s  += __shfl_xor_sync(0xffffffffu, s,  off);
                sq += __shfl_xor_sync(0xffffffffu, sq, off);
            }
            float mean = s * (1.f/128.f);
            float var  = sq * (1.f/128.f) - mean * mean;
            float inv  = rsqrtf(var + 1e-5f);
            int gr = row0 + (h << 6) + rl;
            float4 o;
            o.x = (v.x - mean)*inv*g4.x + b4.x;
            o.y = (v.y - mean)*inv*g4.y + b4.y;
            o.z = (v.z - mean)*inv*g4.z + b4.z;
            o.w = (v.w - mean)*inv*g4.w + b4.w;
            *(float4*)&out[(size_t)gr * EFq + (lane << 2)] = o;
        }
    }
}

// =====================================================================
extern "C" void kernel_launch(void* const* d_in, const int* in_sizes, int n_in,
                              void* d_out, int out_size) {
    const float* X         = (const float*)d_in[0];
    const float* mask      = (const float*)d_in[1];
    const float* atom_mask = (const float*)d_in[4];
    const float* W         = (const float*)d_in[5];
    const float* gamma_    = (const float*)d_in[6];
    const float* beta_     = (const float*)d_in[7];
    float* out = (float*)d_out;

    float* out_tail = (out_size >= Mrows * (EFq + 1)) ? (out + (size_t)Mrows * EFq)
                                                      : nullptr;

    topk_kernel<<<Bq*Lq, 256>>>(X, mask, out_tail);
    buildX2_kernel<<<(Bq*Lq + 255)/256, 256>>>(X);
    prepWfrag_kernel<<<(NCHUNK*4096 + 255)/256, 256>>>(W);

    cudaFuncSetAttribute(fused_hmma_kernel,
                         cudaFuncAttributeMaxDynamicSharedMemorySize, SM_TOTAL);
    fused_hmma_kernel<<<Mrows/BM, 256, SM_TOTAL>>>(atom_mask, gamma_, beta_, out);
}

// round 7
// speedup vs baseline: 1.3674x; 1.3674x over previous
#include <cuda_runtime.h>
#include <cstdint>
#include <math.h>

#define Bq 2
#define Lq 1024
#define Aq 14
#define Kq 30
#define EFq 128
#define EDGE_INq 3152
#define Mrows (Bq*Lq*Kq)      // 61440
#define BM 128
#define NCHUNK 99             // padded K = 3168

typedef uint32_t u32;

// ---- scratch ----
__device__ int g_Eidx[Mrows];
__device__ __align__(16) float g_X2[Bq*Lq*Aq*3];
__device__ __align__(16) float g_Wfrag[NCHUNK*4096];  // fragment-ordered tf32 W

__constant__ float c_freq[8] = {
    1.0f, 0.31622776601683794f, 0.1f, 0.031622776601683794f,
    0.01f, 0.0031622776601683794f, 0.001f, 0.00031622776601683794f
};

__device__ __forceinline__ u32 f2tf32(float v) {
    u32 u; asm("cvt.rna.tf32.f32 %0, %1;" : "=r"(u) : "f"(v)); return u;
}
__device__ __forceinline__ u32 smem_u32(const void* p) {
    u32 a; asm("{ .reg .u64 t; cvta.to.shared.u64 t, %1; cvt.u32.u64 %0, t; }"
               : "=r"(a) : "l"(p));
    return a;
}
__device__ __forceinline__ void mma_tf32(float* d, const u32* a, u32 b0, u32 b1) {
    asm volatile("mma.sync.aligned.m16n8k8.row.col.f32.tf32.tf32.f32 "
        "{%0,%1,%2,%3}, {%4,%5,%6,%7}, {%8,%9}, {%0,%1,%2,%3};"
        : "+f"(d[0]), "+f"(d[1]), "+f"(d[2]), "+f"(d[3])
        : "r"(a[0]), "r"(a[1]), "r"(a[2]), "r"(a[3]), "r"(b0), "r"(b1));
}
#define CP_ASYNC16(dst, src) asm volatile( \
    "cp.async.cg.shared.global [%0], [%1], 16;" :: "r"(dst), "l"(src) : "memory")
#define CP_COMMIT() asm volatile("cp.async.commit_group;" ::: "memory")
#define CP_WAIT1()  asm volatile("cp.async.wait_group 1;" ::: "memory")
#define LDS128(v, addr) asm volatile("ld.shared.v4.f32 {%0,%1,%2,%3}, [%4];" \
    : "=f"(v.x), "=f"(v.y), "=f"(v.z), "=f"(v.w) : "r"(addr))

// =====================================================================
// Kernel 1: topk (correct since round 1)
// =====================================================================
__global__ void topk_kernel(const float* __restrict__ X,
                            const float* __restrict__ mask,
                            float* __restrict__ out_tail) {
    __shared__ float Da[Lq];
    __shared__ float svals[8];
    __shared__ int   sidx[8];
    __shared__ float sDmax;

    int bi  = blockIdx.x;
    int b   = bi >> 10;
    int i   = bi & (Lq - 1);
    int tid = threadIdx.x;

    const float* Xb = X + (size_t)b * Lq * Aq * 3;
    float cx = Xb[(i*Aq+1)*3+0];
    float cy = Xb[(i*Aq+1)*3+1];
    float cz = Xb[(i*Aq+1)*3+2];
    float mi = mask[b*Lq + i];

    float lmax = 0.f;
    for (int j = tid; j < Lq; j += 256) {
        float dx = cx - Xb[(j*Aq+1)*3+0];
        float dy = cy - Xb[(j*Aq+1)*3+1];
        float dz = cz - Xb[(j*Aq+1)*3+2];
        float m2 = mi * mask[b*Lq + j];
        float D  = m2 * sqrtf(dx*dx + dy*dy + dz*dz + 1e-6f);
        Da[j] = D;
        lmax = fmaxf(lmax, D);
    }
    #pragma unroll
    for (int off = 16; off; off >>= 1)
        lmax = fmaxf(lmax, __shfl_xor_sync(0xffffffffu, lmax, off));
    if ((tid & 31) == 0) svals[tid >> 5] = lmax;
    __syncthreads();
    if (tid == 0) {
        float m = svals[0];
        for (int w = 1; w < 8; w++) m = fmaxf(m, svals[w]);
        sDmax = m;
    }
    __syncthreads();
    float Dmax = sDmax;
    for (int j = tid; j < Lq; j += 256) {
        float m2 = mi * mask[b*Lq + j];
        Da[j] += 2.f * (1.f - m2) * Dmax;
    }
    __syncthreads();

    for (int k = 0; k < Kq; k++) {
        float bv = 3.4e38f; int bj = 0x7fffffff;
        for (int j = tid; j < Lq; j += 256) {
            float v = Da[j];
            if (v < bv) { bv = v; bj = j; }
        }
        #pragma unroll
        for (int off = 16; off; off >>= 1) {
            float ov = __shfl_down_sync(0xffffffffu, bv, off);
            int   oj = __shfl_down_sync(0xffffffffu, bj, off);
            if (ov < bv || (ov == bv && oj < bj)) { bv = ov; bj = oj; }
        }
        if ((tid & 31) == 0) { svals[tid >> 5] = bv; sidx[tid >> 5] = bj; }
        __syncthreads();
        if (tid == 0) {
            for (int w = 1; w < 8; w++) {
                float v = svals[w]; int jj = sidx[w];
                if (v < bv || (v == bv && jj < bj)) { bv = v; bj = jj; }
            }
            int orow = bi * Kq + k;
            g_Eidx[orow] = bj;
            if (out_tail) out_tail[orow] = (float)bj;
            Da[bj] = 3.4e38f;
        }
        __syncthreads();
    }
}

// =====================================================================
// Kernel 2: build X2 with virtual Cb
// =====================================================================
__global__ void buildX2_kernel(const float* __restrict__ X) {
    int t = blockIdx.x * blockDim.x + threadIdx.x;
    if (t >= Bq * Lq) return;
    const float* xr = X + (size_t)t * Aq * 3;
    float* o = g_X2 + (size_t)t * Aq * 3;
    #pragma unroll
    for (int a = 0; a < Aq*3; a++) o[a] = xr[a];
    float Nx = xr[0],  Ny = xr[1],  Nz = xr[2];
    float Cax= xr[3],  Cay= xr[4],  Caz= xr[5];
    float Cx = xr[6],  Cy = xr[7],  Cz = xr[8];
    float bx = Cax - Nx, by = Cay - Ny, bz = Caz - Nz;
    float cx = Cx - Cax, cy = Cy - Cay, cz = Cz - Caz;
    float ax = by*cz - bz*cy;
    float ay = bz*cx - bx*cz;
    float az = bx*cy - by*cx;
    o[12] = -0.58273431f*ax + 0.56802827f*bx - 0.54067466f*cx + Cax;
    o[13] = -0.58273431f*ay + 0.56802827f*by - 0.54067466f*cy + Cay;
    o[14] = -0.58273431f*az + 0.56802827f*bz - 0.54067466f*cz + Caz;
}

// =====================================================================
// Kernel 3: pack W into SMEM-fragment order (per chunk, float index):
//   e(bits0-1) lane(2-6) q(7-8) s(9-10) wn(11)
//   nt = 2q + (e>>1), half = e&1
//   n = wn*64 + nt*8 + (lane>>2);  c = k*32 + s*8 + (lane&3) + half*4
// =====================================================================
__global__ void prepWfrag_kernel(const float* __restrict__ W) {
    int t = blockIdx.x * blockDim.x + threadIdx.x;
    if (t >= NCHUNK * 4096) return;
    int e    = t & 3;
    int lane = (t >> 2) & 31;
    int q    = (t >> 7) & 3;
    int s    = (t >> 9) & 3;
    int wn   = (t >> 11) & 1;
    int k    = t >> 12;
    int nt   = 2*q + (e >> 1);
    int half = e & 1;
    int n = wn*64 + nt*8 + (lane >> 2);
    int c = k*32 + s*8 + (lane & 3) + half*4;
    float v = (c < EDGE_INq) ? W[(size_t)n * EDGE_INq + c] : 0.f;
    g_Wfrag[t] = __uint_as_float(f2tf32(v));
}

// =====================================================================
// Kernel 4: fused featuregen-in-registers + mma.sync tf32 + LayerNorm
// B triple-buffered in SMEM via cp.async, fragment-ordered (LDS.128 x4 per s)
// =====================================================================
// byte offsets in dynamic smem
#define SM_SBF   0          // 3 * 16384 = 49152
#define SM_SD    49152      // 2*256 f = 2048
#define SM_SCO   51200      // 2048
#define SM_DPOS  53248      // 512
#define SM_IIDX  53760      // 512
#define SM_JIDX  54272      // 512
#define SM_TOTAL 54784
#define ESTRIDE  132        // epilogue tile reuses bytes [0, 33792)

__global__ void __launch_bounds__(256, 2)
fused_hmma_kernel(const float* __restrict__ atom_mask,
                  const float* __restrict__ gamma_,
                  const float* __restrict__ beta_,
                  float* __restrict__ out) {
    extern __shared__ char smc[];
    u32 sb = smem_u32(smc);
    float* sE    = (float*)(smc);               // epilogue reuse
    float* sD    = (float*)(smc + SM_SD);       // [buf][l*128+row]
    float* sCo   = (float*)(smc + SM_SCO);
    float* dposS = (float*)(smc + SM_DPOS);
    int*   iidx  = (int*)(smc + SM_IIDX);
    int*   jidx  = (int*)(smc + SM_JIDX);

    int tid  = threadIdx.x;
    int wid  = tid >> 5, lane = tid & 31;
    int wm   = wid & 3, wn = wid >> 2;
    int lq   = lane >> 2;    // 0..7
    int lr   = lane & 3;     // 0..3
    int row0 = blockIdx.x * BM;

    if (tid < BM) {
        int gr  = row0 + tid;
        int b   = gr / (Lq * Kq);
        int rem = gr - b * (Lq * Kq);
        int i   = rem / Kq;
        int j   = g_Eidx[gr];
        iidx[tid] = b * Lq + i;
        jidx[tid] = b * Lq + j;
        dposS[tid] = (float)(j - i);
    }
    __syncthreads();

    // ---- stage chunk 0 D/co into sD buf 0 ----
    {
        int l = tid >> 7, row = tid & 127;
        int P = -1 + l;
        float D = 0.f, co = 0.f;
        if (P >= 0) {
            const float* xi = g_X2 + iidx[row]*42;     // P==0 -> p=0,q=0
            const float* xj = g_X2 + jidx[row]*42;
            float dx = xi[0]-xj[0], dy = xi[1]-xj[1], dz = xi[2]-xj[2];
            D  = sqrtf(dx*dx + dy*dy + dz*dz + 1e-6f);
            co = (1.f - atom_mask[iidx[row]*14]) * (1.f - atom_mask[jidx[row]*14]);
        }
        sD [(l << 7) + row] = D;
        sCo[(l << 7) + row] = co;
    }
    // ---- issue B copy for chunk 0 into bbuf 0 ----
    {
        const float4* src = (const float4*)g_Wfrag;
        #pragma unroll
        for (int u = 0; u < 4; u++) {
            int a = tid + (u << 8);
            CP_ASYNC16(sb + SM_SBF + a*16, src + a);
        }
        CP_COMMIT();
    }
    __syncthreads();

    float acc[2][8][4];
    #pragma unroll
    for (int mt = 0; mt < 2; mt++)
        #pragma unroll
        for (int nt = 0; nt < 8; nt++)
            #pragma unroll
            for (int c = 0; c < 4; c++) acc[mt][nt][c] = 0.f;

    for (int k = 0; k < NCHUNK; k++) {
        int buf  = k & 1;
        int bbuf = k - (k/3)*3;        // k % 3
        // ---- preload this chunk's D/co into registers ----
        float Dv[2][4], Cv[2][4];
        #pragma unroll
        for (int rr = 0; rr < 4; rr++) {
            int row = (wm << 5) + (rr << 3) + lq;
            Dv[0][rr] = sD [(buf << 8) + row];
            Dv[1][rr] = sD [(buf << 8) + 128 + row];
            Cv[0][rr] = sCo[(buf << 8) + row];
            Cv[1][rr] = sCo[(buf << 8) + 128 + row];
        }
        // ---- stage chunk k+1 D/co into the other sD buffer ----
        if (k + 1 < NCHUNK) {
            int l = tid >> 7, row = tid & 127;
            int P = 2*(k+1) - 1 + l;
            float D = 0.f, co = 0.f;
            if (P < 196) {
                int p = P / 14, q = P - p * 14;
                const float* xi = g_X2 + iidx[row]*42 + p*3;
                const float* xj = g_X2 + jidx[row]*42 + q*3;
                float dx = xi[0]-xj[0], dy = xi[1]-xj[1], dz = xi[2]-xj[2];
                D  = sqrtf(dx*dx + dy*dy + dz*dz + 1e-6f);
                co = (1.f - atom_mask[iidx[row]*14 + p]) *
                     (1.f - atom_mask[jidx[row]*14 + q]);
            }
            sD [((buf^1) << 8) + (l << 7) + row] = D;
            sCo[((buf^1) << 8) + (l << 7) + row] = co;
            // ---- issue B copy for chunk k+1 ----
            int nb = (k+1) - ((k+1)/3)*3;
            const float4* src = (const float4*)(g_Wfrag + ((size_t)(k+1) << 12));
            u32 dst = sb + SM_SBF + (u32)(nb << 14);
            #pragma unroll
            for (int u = 0; u < 4; u++) {
                int a = tid + (u << 8);
                CP_ASYNC16(dst + a*16, src + a);
            }
        }
        CP_COMMIT();
        CP_WAIT1();
        __syncthreads();     // chunk-k B + chunk-k+1 D/co visible to all

        // ---- fragment gen + mma ----
        // FIX: wn stride is 8192 B (2048 floats), was (wn*4)<<9 = 2048 B
        u32 sbase = sb + SM_SBF + (u32)(bbuf << 14) + (u32)(wn << 13) + (u32)(lane << 4);
        #pragma unroll
        for (int s = 0; s < 4; s++) {
            const int l = s >> 1;
            float mu0 = (float)((s & 1)*8 + lr) * 1.3333333333f;
            float mu1 = mu0 + 5.3333333333f;
            u32 afr[2][4];
            #pragma unroll
            for (int mt = 0; mt < 2; mt++) {
                if (k == 0 && s < 2) {
                    int r0 = (wm << 5) + (mt << 4) + lq;
                    float d0 = dposS[r0], d1 = dposS[r0 + 8];
                    float s0a, c0a, s1a, c1a, s0b, c0b, s1b, c1b;
                    sincosf(d0 * c_freq[lr],     &s0a, &c0a);
                    sincosf(d1 * c_freq[lr],     &s1a, &c1a);
                    sincosf(d0 * c_freq[lr + 4], &s0b, &c0b);
                    sincosf(d1 * c_freq[lr + 4], &s1b, &c1b);
                    if (s == 0) {
                        afr[mt][0] = f2tf32(c0a); afr[mt][1] = f2tf32(c1a);
                        afr[mt][2] = f2tf32(c0b); afr[mt][3] = f2tf32(c1b);
                    } else {
                        afr[mt][0] = f2tf32(s0a); afr[mt][1] = f2tf32(s1a);
                        afr[mt][2] = f2tf32(s0b); afr[mt][3] = f2tf32(s1b);
                    }
                } else {
                    float D0 = Dv[l][mt*2],   C0 = Cv[l][mt*2];
                    float D1 = Dv[l][mt*2+1], C1 = Cv[l][mt*2+1];
                    float x0 = (D0 - mu0) * 0.8f;
                    float x1 = (D1 - mu0) * 0.8f;
                    float x2 = (D0 - mu1) * 0.8f;
                    float x3 = (D1 - mu1) * 0.8f;
                    afr[mt][0] = f2tf32(C0 * __expf(-x0*x0));
                    afr[mt][1] = f2tf32(C1 * __expf(-x1*x1));
                    afr[mt][2] = f2tf32(C0 * __expf(-x2*x2));
                    afr[mt][3] = f2tf32(C1 * __expf(-x3*x3));
                }
            }
            u32 saddr = sbase + (u32)(s << 11);
            #pragma unroll
            for (int q = 0; q < 4; q++) {
                float4 bv;
                LDS128(bv, saddr + (u32)(q << 9));
                u32 b0 = __float_as_uint(bv.x), b1 = __float_as_uint(bv.y);
                u32 b2 = __float_as_uint(bv.z), b3 = __float_as_uint(bv.w);
                #pragma unroll
                for (int mt = 0; mt < 2; mt++) {
                    mma_tf32(acc[mt][2*q],     afr[mt], b0, b1);
                    mma_tf32(acc[mt][2*q + 1], afr[mt], b2, b3);
                }
            }
        }
    }

    // ================= epilogue: 2 halves of 64 rows =================
    float4 g4 = *(const float4*)&gamma_[lane << 2];
    float4 b4 = *(const float4*)&beta_ [lane << 2];

    #pragma unroll
    for (int h = 0; h < 2; h++) {
        __syncthreads();
        if ((wm >> 1) == h) {
            #pragma unroll
            for (int mt = 0; mt < 2; mt++) {
                int rl = (wm << 5) + (mt << 4) + lq - (h << 6);
                #pragma unroll
                for (int nt = 0; nt < 8; nt++) {
                    int col = (wn << 6) + (nt << 3) + (lr << 1);
                    *(float2*)&sE[ rl      * ESTRIDE + col] =
                        make_float2(acc[mt][nt][0], acc[mt][nt][1]);
                    *(float2*)&sE[(rl + 8) * ESTRIDE + col] =
                        make_float2(acc[mt][nt][2], acc[mt][nt][3]);
                }
            }
        }
        __syncthreads();
        #pragma unroll
        for (int rr = 0; rr < 8; rr++) {
            int rl = (wid << 3) + rr;
            float4 v = *(const float4*)&sE[rl * ESTRIDE + (lane << 2)];
            float s  = v.x + v.y + v.z + v.w;
            float sq = v.x*v.x + v.y*v.y + v.z*v.z + v.w*v.w;
            #pragma unroll
            for (int off = 16; off; off >>= 1) {
                s  += __shfl_xor_sync(0xffffffffu, s,  off);
                sq += __shfl_xor_sync(0xffffffffu, sq, off);
            }
            float mean = s * (1.f/128.f);
            float var  = sq * (1.f/128.f) - mean * mean;
            float inv  = rsqrtf(var + 1e-5f);
            int gr = row0 + (h << 6) + rl;
            float4 o;
            o.x = (v.x - mean)*inv*g4.x + b4.x;
            o.y = (v.y - mean)*inv*g4.y + b4.y;
            o.z = (v.z - mean)*inv*g4.z + b4.z;
            o.w = (v.w - mean)*inv*g4.w + b4.w;
            *(float4*)&out[(size_t)gr * EFq + (lane << 2)] = o;
        }
    }
}

// =====================================================================
extern "C" void kernel_launch(void* const* d_in, const int* in_sizes, int n_in,
                              void* d_out, int out_size) {
    const float* X         = (const float*)d_in[0];
    const float* mask      = (const float*)d_in[1];
    const float* atom_mask = (const float*)d_in[4];
    const float* W         = (const float*)d_in[5];
    const float* gamma_    = (const float*)d_in[6];
    const float* beta_     = (const float*)d_in[7];
    float* out = (float*)d_out;

    float* out_tail = (out_size >= Mrows * (EFq + 1)) ? (out + (size_t)Mrows * EFq)
                                                      : nullptr;

    topk_kernel<<<Bq*Lq, 256>>>(X, mask, out_tail);
    buildX2_kernel<<<(Bq*Lq + 255)/256, 256>>>(X);
    prepWfrag_kernel<<<(NCHUNK*4096 + 255)/256, 256>>>(W);

    cudaFuncSetAttribute(fused_hmma_kernel,
                         cudaFuncAttributeMaxDynamicSharedMemorySize, SM_TOTAL);
    fused_hmma_kernel<<<Mrows/BM, 256, SM_TOTAL>>>(atom_mask, gamma_, beta_, out);
}

// round 8
// speedup vs baseline: 1.4182x; 1.0371x over previous
#include <cuda_runtime.h>
#include <cstdint>
#include <math.h>

#define Bq 2
#define Lq 1024
#define Aq 14
#define Kq 30
#define EFq 128
#define EDGE_INq 3152
#define Mrows (Bq*Lq*Kq)      // 61440
#define BM 128
#define NCHUNK 99             // padded K = 3168

typedef uint32_t u32;

// ---- scratch ----
__device__ int g_Eidx[Mrows];
__device__ __align__(16) float g_X2[Bq*Lq*Aq*3];
__device__ __align__(16) float g_Wfrag[NCHUNK*4096];  // fragment-ordered tf32 W

__constant__ float c_freq[8] = {
    1.0f, 0.31622776601683794f, 0.1f, 0.031622776601683794f,
    0.01f, 0.0031622776601683794f, 0.001f, 0.00031622776601683794f
};

__device__ __forceinline__ u32 f2tf32(float v) {
    u32 u; asm("cvt.rna.tf32.f32 %0, %1;" : "=r"(u) : "f"(v)); return u;
}
__device__ __forceinline__ float ex2f(float x) {
    float r; asm("ex2.approx.f32 %0, %1;" : "=f"(r) : "f"(x)); return r;
}
__device__ __forceinline__ u32 smem_u32(const void* p) {
    u32 a; asm("{ .reg .u64 t; cvta.to.shared.u64 t, %1; cvt.u32.u64 %0, t; }"
               : "=r"(a) : "l"(p));
    return a;
}
__device__ __forceinline__ void mma_tf32(float* d, const u32* a, u32 b0, u32 b1) {
    asm volatile("mma.sync.aligned.m16n8k8.row.col.f32.tf32.tf32.f32 "
        "{%0,%1,%2,%3}, {%4,%5,%6,%7}, {%8,%9}, {%0,%1,%2,%3};"
        : "+f"(d[0]), "+f"(d[1]), "+f"(d[2]), "+f"(d[3])
        : "r"(a[0]), "r"(a[1]), "r"(a[2]), "r"(a[3]), "r"(b0), "r"(b1));
}
#define CP_ASYNC16(dst, src) asm volatile( \
    "cp.async.cg.shared.global [%0], [%1], 16;" :: "r"(dst), "l"(src) : "memory")
#define CP_COMMIT() asm volatile("cp.async.commit_group;" ::: "memory")
#define CP_WAIT1()  asm volatile("cp.async.wait_group 1;" ::: "memory")
#define LDS128(v, addr) asm volatile("ld.shared.v4.f32 {%0,%1,%2,%3}, [%4];" \
    : "=f"(v.x), "=f"(v.y), "=f"(v.z), "=f"(v.w) : "r"(addr))
#define STS128(addr, a0, a1, a2, a3) asm volatile( \
    "st.shared.v4.b32 [%0], {%1,%2,%3,%4};" \
    :: "r"(addr), "r"(a0), "r"(a1), "r"(a2), "r"(a3) : "memory")

// =====================================================================
// Kernel 1: topk (correct since round 1)
// =====================================================================
__global__ void topk_kernel(const float* __restrict__ X,
                            const float* __restrict__ mask,
                            float* __restrict__ out_tail) {
    __shared__ float Da[Lq];
    __shared__ float svals[8];
    __shared__ int   sidx[8];
    __shared__ float sDmax;

    int bi  = blockIdx.x;
    int b   = bi >> 10;
    int i   = bi & (Lq - 1);
    int tid = threadIdx.x;

    const float* Xb = X + (size_t)b * Lq * Aq * 3;
    float cx = Xb[(i*Aq+1)*3+0];
    float cy = Xb[(i*Aq+1)*3+1];
    float cz = Xb[(i*Aq+1)*3+2];
    float mi = mask[b*Lq + i];

    float lmax = 0.f;
    for (int j = tid; j < Lq; j += 256) {
        float dx = cx - Xb[(j*Aq+1)*3+0];
        float dy = cy - Xb[(j*Aq+1)*3+1];
        float dz = cz - Xb[(j*Aq+1)*3+2];
        float m2 = mi * mask[b*Lq + j];
        float D  = m2 * sqrtf(dx*dx + dy*dy + dz*dz + 1e-6f);
        Da[j] = D;
        lmax = fmaxf(lmax, D);
    }
    #pragma unroll
    for (int off = 16; off; off >>= 1)
        lmax = fmaxf(lmax, __shfl_xor_sync(0xffffffffu, lmax, off));
    if ((tid & 31) == 0) svals[tid >> 5] = lmax;
    __syncthreads();
    if (tid == 0) {
        float m = svals[0];
        for (int w = 1; w < 8; w++) m = fmaxf(m, svals[w]);
        sDmax = m;
    }
    __syncthreads();
    float Dmax = sDmax;
    for (int j = tid; j < Lq; j += 256) {
        float m2 = mi * mask[b*Lq + j];
        Da[j] += 2.f * (1.f - m2) * Dmax;
    }
    __syncthreads();

    for (int k = 0; k < Kq; k++) {
        float bv = 3.4e38f; int bj = 0x7fffffff;
        for (int j = tid; j < Lq; j += 256) {
            float v = Da[j];
            if (v < bv) { bv = v; bj = j; }
        }
        #pragma unroll
        for (int off = 16; off; off >>= 1) {
            float ov = __shfl_down_sync(0xffffffffu, bv, off);
            int   oj = __shfl_down_sync(0xffffffffu, bj, off);
            if (ov < bv || (ov == bv && oj < bj)) { bv = ov; bj = oj; }
        }
        if ((tid & 31) == 0) { svals[tid >> 5] = bv; sidx[tid >> 5] = bj; }
        __syncthreads();
        if (tid == 0) {
            for (int w = 1; w < 8; w++) {
                float v = svals[w]; int jj = sidx[w];
                if (v < bv || (v == bv && jj < bj)) { bv = v; bj = jj; }
            }
            int orow = bi * Kq + k;
            g_Eidx[orow] = bj;
            if (out_tail) out_tail[orow] = (float)bj;
            Da[bj] = 3.4e38f;
        }
        __syncthreads();
    }
}

// =====================================================================
// Kernel 2: build X2 with virtual Cb
// =====================================================================
__global__ void buildX2_kernel(const float* __restrict__ X) {
    int t = blockIdx.x * blockDim.x + threadIdx.x;
    if (t >= Bq * Lq) return;
    const float* xr = X + (size_t)t * Aq * 3;
    float* o = g_X2 + (size_t)t * Aq * 3;
    #pragma unroll
    for (int a = 0; a < Aq*3; a++) o[a] = xr[a];
    float Nx = xr[0],  Ny = xr[1],  Nz = xr[2];
    float Cax= xr[3],  Cay= xr[4],  Caz= xr[5];
    float Cx = xr[6],  Cy = xr[7],  Cz = xr[8];
    float bx = Cax - Nx, by = Cay - Ny, bz = Caz - Nz;
    float cx = Cx - Cax, cy = Cy - Cay, cz = Cz - Caz;
    float ax = by*cz - bz*cy;
    float ay = bz*cx - bx*cz;
    float az = bx*cy - by*cx;
    o[12] = -0.58273431f*ax + 0.56802827f*bx - 0.54067466f*cx + Cax;
    o[13] = -0.58273431f*ay + 0.56802827f*by - 0.54067466f*cy + Cay;
    o[14] = -0.58273431f*az + 0.56802827f*bz - 0.54067466f*cz + Caz;
}

// =====================================================================
// Kernel 3: pack W into SMEM-fragment order (per chunk, float index):
//   e(bits0-1) lane(2-6) q(7-8) s(9-10) wn(11)
//   nt = 2q + (e>>1), half = e&1
//   n = wn*64 + nt*8 + (lane>>2);  c = k*32 + s*8 + (lane&3) + half*4
// =====================================================================
__global__ void prepWfrag_kernel(const float* __restrict__ W) {
    int t = blockIdx.x * blockDim.x + threadIdx.x;
    if (t >= NCHUNK * 4096) return;
    int e    = t & 3;
    int lane = (t >> 2) & 31;
    int q    = (t >> 7) & 3;
    int s    = (t >> 9) & 3;
    int wn   = (t >> 11) & 1;
    int k    = t >> 12;
    int nt   = 2*q + (e >> 1);
    int half = e & 1;
    int n = wn*64 + nt*8 + (lane >> 2);
    int c = k*32 + s*8 + (lane & 3) + half*4;
    float v = (c < EDGE_INq) ? W[(size_t)n * EDGE_INq + c] : 0.f;
    g_Wfrag[t] = __uint_as_float(f2tf32(v));
}

// =====================================================================
// Kernel 4: fused featuregen + mma.sync tf32 + LayerNorm
// A-fragment producer/consumer sharing: warp (wm,wn) PRODUCES s={2wn,2wn+1}
// into sAfr, all warps CONSUME all 4 s after a barrier. Halves expf/cvt.
// =====================================================================
// byte offsets in dynamic smem
#define SM_SBF   0          // 3 * 16384 = 49152 (B triple buffer)
#define SM_SD    49152      // 2*256 f = 2048
#define SM_SCO   51200      // 2048
#define SM_DPOS  53248      // 512
#define SM_IIDX  53760      // 512
#define SM_JIDX  54272      // 512
#define SM_AFR   54784      // 4 wm x 4 s x 2 mt x 512B = 16384
#define SM_TOTAL 71168
#define ESTRIDE  132        // epilogue tile reuses bytes [0, 33792)

__global__ void __launch_bounds__(256, 2)
fused_hmma_kernel(const float* __restrict__ atom_mask,
                  const float* __restrict__ gamma_,
                  const float* __restrict__ beta_,
                  float* __restrict__ out) {
    extern __shared__ char smc[];
    u32 sb = smem_u32(smc);
    float* sE    = (float*)(smc);               // epilogue reuse
    float* sD    = (float*)(smc + SM_SD);       // [buf][l*128+row]
    float* sCo   = (float*)(smc + SM_SCO);
    float* dposS = (float*)(smc + SM_DPOS);
    int*   iidx  = (int*)(smc + SM_IIDX);
    int*   jidx  = (int*)(smc + SM_JIDX);

    int tid  = threadIdx.x;
    int wid  = tid >> 5, lane = tid & 31;
    int wm   = wid & 3, wn = wid >> 2;
    int lq   = lane >> 2;    // 0..7
    int lr   = lane & 3;     // 0..3
    int row0 = blockIdx.x * BM;

    if (tid < BM) {
        int gr  = row0 + tid;
        int b   = gr / (Lq * Kq);
        int rem = gr - b * (Lq * Kq);
        int i   = rem / Kq;
        int j   = g_Eidx[gr];
        iidx[tid] = b * Lq + i;
        jidx[tid] = b * Lq + j;
        dposS[tid] = (float)(j - i);
    }
    __syncthreads();

    // ---- stage chunk 0 D/co into sD buf 0 ----
    {
        int l = tid >> 7, row = tid & 127;
        int P = -1 + l;
        float D = 0.f, co = 0.f;
        if (P >= 0) {
            const float* xi = g_X2 + iidx[row]*42;     // P==0 -> p=0,q=0
            const float* xj = g_X2 + jidx[row]*42;
            float dx = xi[0]-xj[0], dy = xi[1]-xj[1], dz = xi[2]-xj[2];
            D  = sqrtf(dx*dx + dy*dy + dz*dz + 1e-6f);
            co = (1.f - atom_mask[iidx[row]*14]) * (1.f - atom_mask[jidx[row]*14]);
        }
        sD [(l << 7) + row] = D;
        sCo[(l << 7) + row] = co;
    }
    // ---- issue B copy for chunk 0 into bbuf 0 ----
    {
        const float4* src = (const float4*)g_Wfrag;
        #pragma unroll
        for (int u = 0; u < 4; u++) {
            int a = tid + (u << 8);
            CP_ASYNC16(sb + SM_SBF + a*16, src + a);
        }
        CP_COMMIT();
    }
    __syncthreads();

    float acc[2][8][4];
    #pragma unroll
    for (int mt = 0; mt < 2; mt++)
        #pragma unroll
        for (int nt = 0; nt < 8; nt++)
            #pragma unroll
            for (int c = 0; c < 4; c++) acc[mt][nt][c] = 0.f;

    for (int k = 0; k < NCHUNK; k++) {
        int buf  = k & 1;
        int bbuf = k - (k/3)*3;        // k % 3
        // ---- stage chunk k+1 D/co into the other sD buffer ----
        if (k + 1 < NCHUNK) {
            int l = tid >> 7, row = tid & 127;
            int P = 2*(k+1) - 1 + l;
            float D = 0.f, co = 0.f;
            if (P < 196) {
                int p = P / 14, q = P - p * 14;
                const float* xi = g_X2 + iidx[row]*42 + p*3;
                const float* xj = g_X2 + jidx[row]*42 + q*3;
                float dx = xi[0]-xj[0], dy = xi[1]-xj[1], dz = xi[2]-xj[2];
                D  = sqrtf(dx*dx + dy*dy + dz*dz + 1e-6f);
                co = (1.f - atom_mask[iidx[row]*14 + p]) *
                     (1.f - atom_mask[jidx[row]*14 + q]);
            }
            sD [((buf^1) << 8) + (l << 7) + row] = D;
            sCo[((buf^1) << 8) + (l << 7) + row] = co;
            // ---- issue B copy for chunk k+1 ----
            int nb = (k+1) - ((k+1)/3)*3;
            const float4* src = (const float4*)(g_Wfrag + ((size_t)(k+1) << 12));
            u32 dst = sb + SM_SBF + (u32)(nb << 14);
            #pragma unroll
            for (int u = 0; u < 4; u++) {
                int a = tid + (u << 8);
                CP_ASYNC16(dst + a*16, src + a);
            }
        }
        CP_COMMIT();
        CP_WAIT1();
        __syncthreads();     // chunk-k B ready; chunk-k+1 D/co visible

        // ===== PHASE A: produce A fragments for s in {2wn, 2wn+1} =====
        // this warp's l = wn; rows (wm<<5)+(rr<<3)+lq
        {
            float Dp[4], Cp[4];
            #pragma unroll
            for (int rr = 0; rr < 4; rr++) {
                int row = (wm << 5) + (rr << 3) + lq;
                Dp[rr] = sD [(buf << 8) + (wn << 7) + row];
                Cp[rr] = sCo[(buf << 8) + (wn << 7) + row];
            }
            #pragma unroll
            for (int sp = 0; sp < 2; sp++) {
                int s = (wn << 1) + sp;
                float mu0 = (float)(((s & 1) << 3) + lr) * 1.3333333333f;
                float mu1 = mu0 + 5.3333333333f;
                #pragma unroll
                for (int mt = 0; mt < 2; mt++) {
                    u32 v0, v1, v2, v3;
                    if (k == 0 && wn == 0) {
                        // posenc: s=0 -> cos, s=1 -> sin
                        int r0 = (wm << 5) + (mt << 4) + lq;
                        float d0 = dposS[r0], d1 = dposS[r0 + 8];
                        float s0a, c0a, s1a, c1a, s0b, c0b, s1b, c1b;
                        sincosf(d0 * c_freq[lr],     &s0a, &c0a);
                        sincosf(d1 * c_freq[lr],     &s1a, &c1a);
                        sincosf(d0 * c_freq[lr + 4], &s0b, &c0b);
                        sincosf(d1 * c_freq[lr + 4], &s1b, &c1b);
                        if (sp == 0) {
                            v0 = f2tf32(c0a); v1 = f2tf32(c1a);
                            v2 = f2tf32(c0b); v3 = f2tf32(c1b);
                        } else {
                            v0 = f2tf32(s0a); v1 = f2tf32(s1a);
                            v2 = f2tf32(s0b); v3 = f2tf32(s1b);
                        }
                    } else {
                        float D0 = Dp[mt*2],   C0 = Cp[mt*2];
                        float D1 = Dp[mt*2+1], C1 = Cp[mt*2+1];
                        float t0 = D0 - mu0, t1 = D1 - mu0;
                        float t2 = D0 - mu1, t3 = D1 - mu1;
                        v0 = f2tf32(C0 * ex2f(t0*t0*-0.9233248262f));
                        v1 = f2tf32(C1 * ex2f(t1*t1*-0.9233248262f));
                        v2 = f2tf32(C0 * ex2f(t2*t2*-0.9233248262f));
                        v3 = f2tf32(C1 * ex2f(t3*t3*-0.9233248262f));
                    }
                    u32 dst = sb + SM_AFR
                            + (u32)(((((wm << 2) + s) << 1) + mt) << 9)
                            + (u32)(lane << 4);
                    STS128(dst, v0, v1, v2, v3);
                }
            }
        }
        __syncthreads();     // sAfr(k) ready for all warps

        // ===== PHASE B: consume fragments + MMA =====
        u32 sbase = sb + SM_SBF + (u32)(bbuf << 14) + (u32)(wn << 13) + (u32)(lane << 4);
        u32 abase = sb + SM_AFR + (u32)(wm << 12) + (u32)(lane << 4);
        #pragma unroll
        for (int s = 0; s < 4; s++) {
            u32 afr[2][4];
            #pragma unroll
            for (int mt = 0; mt < 2; mt++) {
                float4 av;
                LDS128(av, abase + (u32)((((s << 1) + mt)) << 9));
                afr[mt][0] = __float_as_uint(av.x);
                afr[mt][1] = __float_as_uint(av.y);
                afr[mt][2] = __float_as_uint(av.z);
                afr[mt][3] = __float_as_uint(av.w);
            }
            u32 saddr = sbase + (u32)(s << 11);
            #pragma unroll
            for (int q = 0; q < 4; q++) {
                float4 bv;
                LDS128(bv, saddr + (u32)(q << 9));
                u32 b0 = __float_as_uint(bv.x), b1 = __float_as_uint(bv.y);
                u32 b2 = __float_as_uint(bv.z), b3 = __float_as_uint(bv.w);
                #pragma unroll
                for (int mt = 0; mt < 2; mt++) {
                    mma_tf32(acc[mt][2*q],     afr[mt], b0, b1);
                    mma_tf32(acc[mt][2*q + 1], afr[mt], b2, b3);
                }
            }
        }
    }

    // ================= epilogue: 2 halves of 64 rows =================
    float4 g4 = *(const float4*)&gamma_[lane << 2];
    float4 b4 = *(const float4*)&beta_ [lane << 2];

    #pragma unroll
    for (int h = 0; h < 2; h++) {
        __syncthreads();
        if ((wm >> 1) == h) {
            #pragma unroll
            for (int mt = 0; mt < 2; mt++) {
                int rl = (wm << 5) + (mt << 4) + lq - (h << 6);
                #pragma unroll
                for (int nt = 0; nt < 8; nt++) {
                    int col = (wn << 6) + (nt << 3) + (lr << 1);
                    *(float2*)&sE[ rl      * ESTRIDE + col] =
                        make_float2(acc[mt][nt][0], acc[mt][nt][1]);
                    *(float2*)&sE[(rl + 8) * ESTRIDE + col] =
                        make_float2(acc[mt][nt][2], acc[mt][nt][3]);
                }
            }
        }
        __syncthreads();
        #pragma unroll
        for (int rr = 0; rr < 8; rr++) {
            int rl = (wid << 3) + rr;
            float4 v = *(const float4*)&sE[rl * ESTRIDE + (lane << 2)];
            float s  = v.x + v.y + v.z + v.w;
            float sq = v.x*v.x + v.y*v.y + v.z*v.z + v.w*v.w;
            #pragma unroll
            for (int off = 16; off; off >>= 1) {
                s  += __shfl_xor_sync(0xffffffffu, s,  off);
                sq += __shfl_xor_sync(0xffffffffu, sq, off);
            }
            float mean = s * (1.f/128.f);
            float var  = sq * (1.f/128.f) - mean * mean;
            float inv  = rsqrtf(var + 1e-5f);
            int gr = row0 + (h << 6) + rl;
            float4 o;
            o.x = (v.x - mean)*inv*g4.x + b4.x;
            o.y = (v.y - mean)*inv*g4.y + b4.y;
            o.z = (v.z - mean)*inv*g4.z + b4.z;
            o.w = (v.w - mean)*inv*g4.w + b4.w;
            *(float4*)&out[(size_t)gr * EFq + (lane << 2)] = o;
        }
    }
}

// =====================================================================
extern "C" void kernel_launch(void* const* d_in, const int* in_sizes, int n_in,
                              void* d_out, int out_size) {
    const float* X         = (const float*)d_in[0];
    const float* mask      = (const float*)d_in[1];
    const float* atom_mask = (const float*)d_in[4];
    const float* W         = (const float*)d_in[5];
    const float* gamma_    = (const float*)d_in[6];
    const float* beta_     = (const float*)d_in[7];
    float* out = (float*)d_out;

    float* out_tail = (out_size >= Mrows * (EFq + 1)) ? (out + (size_t)Mrows * EFq)
                                                      : nullptr;

    topk_kernel<<<Bq*Lq, 256>>>(X, mask, out_tail);
    buildX2_kernel<<<(Bq*Lq + 255)/256, 256>>>(X);
    prepWfrag_kernel<<<(NCHUNK*4096 + 255)/256, 256>>>(W);

    cudaFuncSetAttribute(fused_hmma_kernel,
                         cudaFuncAttributeMaxDynamicSharedMemorySize, SM_TOTAL);
    fused_hmma_kernel<<<Mrows/BM, 256, SM_TOTAL>>>(atom_mask, gamma_, beta_, out);
}